// round 15
// baseline (speedup 1.0000x reference)
#include <cuda_runtime.h>
#include <cuda_bf16.h>
#include <cstdint>
#include <math.h>

#define N_NODES   8192
#define N_EDGES   16384
#define N_GRAPHS  256
#define N_STEMS   2048
#define N_JBONDS  1024
#define DIM       64
#define NUM_FEAT  14
#define NUM_OUT   105

// ---------------- scratch (device globals; no allocations allowed) ----------------
__device__ __nv_bfloat16 g_w2r[65 * 64 * 64];   // W2 rearranged [chunk k][o][i] bf16; chunk 64 = B2
__device__ float g_h1f[N_EDGES * DIM];          // edge-net hidden (fp32)
__device__ uint32_t g_rtu[64 * 64];             // conv_root^T  [o][pair-permuted k] tf32 bits
__device__ uint32_t g_wihTu[192 * 64];          // gru_w_ih^T [o][pair-permuted k] tf32 bits
__device__ uint32_t g_whhTu[192 * 64];          // gru_w_hh^T [o][pair-permuted k] tf32 bits
__device__ float g_h[N_NODES * DIM];            // node state
__device__ float g_agg[N_NODES * DIM];          // scatter accumulator
__device__ float g_deg[N_NODES];                // becomes 1/max(deg,1)
__device__ float g_q[DIM];

__device__ __forceinline__ float lrelu(float v) { return v > 0.f ? v : 0.01f * v; }
__device__ __forceinline__ float sigm(float v)  { return 1.f / (1.f + expf(-v)); }

__device__ __forceinline__ void mma_bf16(float* c, const uint32_t* a, const uint32_t* b) {
    asm volatile(
        "mma.sync.aligned.m16n8k16.row.col.f32.bf16.bf16.f32 "
        "{%0,%1,%2,%3}, {%4,%5,%6,%7}, {%8,%9}, {%0,%1,%2,%3};"
        : "+f"(c[0]), "+f"(c[1]), "+f"(c[2]), "+f"(c[3])
        : "r"(a[0]), "r"(a[1]), "r"(a[2]), "r"(a[3]), "r"(b[0]), "r"(b[1]));
}

__device__ __forceinline__ uint32_t hmul2b(uint32_t a, uint32_t s) {
    uint32_t r;
    asm("mul.bf16x2 %0, %1, %2;" : "=r"(r) : "r"(a), "r"(s));
    return r;
}

__device__ __forceinline__ uint32_t f2tf32(float f) {
    uint32_t r;
    asm("cvt.rna.tf32.f32 %0, %1;" : "=r"(r) : "f"(f));
    return r;
}

__device__ __forceinline__ void mma_tf32(float* c, const uint32_t* a, const uint32_t* b) {
    asm volatile(
        "mma.sync.aligned.m16n8k8.row.col.f32.tf32.tf32.f32 "
        "{%0,%1,%2,%3}, {%4,%5,%6,%7}, {%8,%9}, {%0,%1,%2,%3};"
        : "+f"(c[0]), "+f"(c[1]), "+f"(c[2]), "+f"(c[3])
        : "r"(a[0]), "r"(a[1]), "r"(a[2]), "r"(a[3]), "r"(b[0]), "r"(b[1]));
}

// pair-permuted storage index: j = ks*8 + t4*2 + p  <->  k = ks*8 + t4 + 4*p
__device__ __forceinline__ int pp_k(int j) {
    return (j & ~7) + ((j & 7) >> 1) + (j & 1) * 4;
}

// ---------------- degree / init ----------------
__global__ void zero_deg_kernel() {
    g_deg[blockIdx.x * 256 + threadIdx.x] = 0.f;
}
__global__ void deg_kernel(const int* __restrict__ dst) {
    int e = blockIdx.x * 256 + threadIdx.x;
    if (e < N_EDGES) atomicAdd(&g_deg[dst[e]], 1.0f);
}
__global__ void invdeg_kernel() {
    int i = blockIdx.x * 256 + threadIdx.x;
    g_deg[i] = 1.0f / fmaxf(g_deg[i], 1.0f);
}
__global__ void zero_agg_kernel() {
    int i = blockIdx.x * 256 + threadIdx.x;
    ((float4*)g_agg)[i] = make_float4(0.f, 0.f, 0.f, 0.f);
}

// ---------------- lin0: h = lrelu(x @ W + b) ----------------
__global__ void lin0_kernel(const float* __restrict__ x,
                            const float* __restrict__ W,
                            const float* __restrict__ b) {
    int tid = blockIdx.x * 256 + threadIdx.x;
    int n = tid >> 6, o = tid & 63;
    float acc = b[o];
#pragma unroll
    for (int i = 0; i < NUM_FEAT; i++) acc += x[n * NUM_FEAT + i] * W[i * DIM + o];
    g_h[(size_t)n * DIM + o] = lrelu(acc);
}

// ---------------- edge net hidden: h1 = lrelu(ea @ W1 + b1), fp32 ----------------
__global__ void h1_kernel(const float* __restrict__ ea,
                          const float* __restrict__ W1,
                          const float* __restrict__ b1) {
    int tid = blockIdx.x * 256 + threadIdx.x;
    int e = tid >> 6, k = tid & 63;
    float acc = b1[k];
#pragma unroll
    for (int i = 0; i < 4; i++) acc += ea[e * 4 + i] * W1[i * DIM + k];
    g_h1f[(size_t)e * DIM + k] = lrelu(acc);
}

// ---------------- W2 rearrange: g_w2r[k][o][i] = W2[k][i*64+o]; chunk 64 = B2 ------
__global__ void w2r_kernel(const float* __restrict__ W2, const float* __restrict__ b2) {
    int idx = blockIdx.x * 256 + threadIdx.x;
    if (idx >= 65 * 4096) return;
    int c = idx >> 12, r = idx & 4095;
    int o = r >> 6, i = r & 63;
    float v = (c < 64) ? W2[(c << 12) + (i << 6) + o] : b2[(i << 6) + o];
    g_w2r[idx] = __float2bfloat16(v);
}

// ---------------- GRU/root weights -> transposed, pair-permuted tf32 bits ----------
__global__ void prep_weights_kernel(const float* __restrict__ R,
                                    const float* __restrict__ Wih,
                                    const float* __restrict__ Whh) {
    int i = blockIdx.x * 256 + threadIdx.x;     // 0 .. 28671
    if (i < 4096) {
        int o = i >> 6, j = i & 63;
        g_rtu[o * 64 + j] = f2tf32(R[pp_k(j) * 64 + o]);
    } else if (i < 4096 + 12288) {
        int q = i - 4096;
        int o = q >> 6, j = q & 63;
        g_wihTu[o * 64 + j] = f2tf32(Wih[pp_k(j) * 192 + o]);
    } else {
        int q = i - 4096 - 12288;
        int o = q >> 6, j = q & 63;
        g_whhTu[o * 64 + j] = f2tf32(Whh[pp_k(j) * 192 + o]);
    }
}

// ================= fused factorized message GEMM (k-split) ========================
#define MSG_SMEM_W2   0
#define MSG_SMEM_V    73728
#define MSG_SMEM_H1   92160
#define MSG_SMEM_DS   109056
#define MSG_SMEM_SS   109568
#define MSG_SMEM_TOTAL 110080
#define W2BUF_BYTES   36864

__device__ __forceinline__ void prefetch_w2(int base_chunk, int nch, int buf,
                                            int tid, uint32_t smem_base) {
    int tasks = nch * 512;                      // nch * 64 rows * 8 segs
    for (int idx = tid; idx < tasks; idx += 256) {
        int cc = idx >> 9;
        int o  = (idx >> 3) & 63;
        int s  = idx & 7;
        const __nv_bfloat16* gp = &g_w2r[((size_t)(base_chunk + cc) * 64 + o) * 64 + s * 8];
        uint32_t sp = smem_base + MSG_SMEM_W2 + buf * W2BUF_BYTES
                      + ((cc * 64 + o) * 72 + s * 8) * 2;
        asm volatile("cp.async.cg.shared.global [%0], [%1], 16;" :: "r"(sp), "l"(gp));
    }
    asm volatile("cp.async.commit_group;" ::: "memory");
}

__global__ __launch_bounds__(256, 2) void msg_gemm(const int* __restrict__ src,
                                                   const int* __restrict__ dst) {
    extern __shared__ char smem[];
    __nv_bfloat16* vsm = (__nv_bfloat16*)(smem + MSG_SMEM_V);
    uint32_t* h1b = (uint32_t*)(smem + MSG_SMEM_H1);
    int* dssm = (int*)(smem + MSG_SMEM_DS);
    int* ssm  = (int*)(smem + MSG_SMEM_SS);
    uint32_t smem_base = (uint32_t)__cvta_generic_to_shared(smem);

    int tid = threadIdx.x;
    int ebid = blockIdx.x & 127;
    int khalf = blockIdx.x >> 7;
    int e0 = ebid * 128;
    int kbase = khalf * 32;

    if (tid < 128) {
        ssm[tid] = src[e0 + tid];
        dssm[tid] = dst[e0 + tid];
    }
    prefetch_w2(kbase, 4, 0, tid, smem_base);
    __syncthreads();                            // ssm visible

#pragma unroll
    for (int p = 0; p < 8; p++) {
        int idx = tid + p * 256;                // 2048 tasks: 128 rows x 16 segs
        int row = idx >> 4, seg = idx & 15;
        int s = ssm[row];
        float4 v = *(const float4*)&g_h[(size_t)s * 64 + seg * 4];
        __nv_bfloat162 p0 = __floats2bfloat162_rn(v.x, v.y);
        __nv_bfloat162 p1 = __floats2bfloat162_rn(v.z, v.w);
        uint2 u; u.x = *(uint32_t*)&p0; u.y = *(uint32_t*)&p1;
        *(uint2*)&vsm[row * 72 + seg * 4] = u;
    }
#pragma unroll
    for (int p = 0; p < 4; p++) {
        int idx = tid + p * 256;                // 1024 tasks: 128 rows x 8 quads
        int row = idx >> 3, q = idx & 7;
        float4 hv = *(const float4*)&g_h1f[(size_t)(e0 + row) * 64 + kbase + q * 4];
        __nv_bfloat16 b0 = __float2bfloat16(hv.x);
        __nv_bfloat16 b1 = __float2bfloat16(hv.y);
        __nv_bfloat16 b2 = __float2bfloat16(hv.z);
        __nv_bfloat16 b3 = __float2bfloat16(hv.w);
        h1b[row * 33 + q * 4 + 0] = ((uint32_t)*(uint16_t*)&b0) * 0x00010001u;
        h1b[row * 33 + q * 4 + 1] = ((uint32_t)*(uint16_t*)&b1) * 0x00010001u;
        h1b[row * 33 + q * 4 + 2] = ((uint32_t)*(uint16_t*)&b2) * 0x00010001u;
        h1b[row * 33 + q * 4 + 3] = ((uint32_t)*(uint16_t*)&b3) * 0x00010001u;
    }
    __syncthreads();

    int w = tid >> 5, lane = tid & 31;
    int warpM = w >> 1, warpN = w & 1;          // 4 m-warps x 2 n-warps
    int rowbase = warpM * 32;
    int g = lane >> 2, t4 = lane & 3;

    uint32_t vfrag[2][4][4];
#pragma unroll
    for (int mt = 0; mt < 2; mt++)
#pragma unroll
        for (int ks = 0; ks < 4; ks++) {
            int r0 = rowbase + mt * 16 + g;
            int cl = ks * 16 + 2 * t4;
            vfrag[mt][ks][0] = *(const uint32_t*)&vsm[r0 * 72 + cl];
            vfrag[mt][ks][1] = *(const uint32_t*)&vsm[(r0 + 8) * 72 + cl];
            vfrag[mt][ks][2] = *(const uint32_t*)&vsm[r0 * 72 + cl + 8];
            vfrag[mt][ks][3] = *(const uint32_t*)&vsm[(r0 + 8) * 72 + cl + 8];
        }

    float c[2][4][4];
#pragma unroll
    for (int mt = 0; mt < 2; mt++)
#pragma unroll
        for (int ni = 0; ni < 4; ni++)
#pragma unroll
            for (int r = 0; r < 4; r++) c[mt][ni][r] = 0.f;

#pragma unroll 1
    for (int grp = 0; grp < 8; grp++) {
        asm volatile("cp.async.wait_group 0;" ::: "memory");
        __syncthreads();
        int buf = grp & 1;
        if (grp < 7)           prefetch_w2(kbase + (grp + 1) * 4, 4, (grp + 1) & 1, tid, smem_base);
        else if (khalf == 1)   prefetch_w2(64, 1, 0, tid, smem_base);
        const __nv_bfloat16* w2p =
            (const __nv_bfloat16*)(smem + MSG_SMEM_W2 + buf * W2BUF_BYTES);
#pragma unroll 1
        for (int cc = 0; cc < 4; cc++) {
            int kloc = grp * 4 + cc;
            uint32_t hA[2], hB[2];
#pragma unroll
            for (int mt = 0; mt < 2; mt++) {
                int rA = rowbase + mt * 16 + g;
                hA[mt] = h1b[rA * 33 + kloc];
                hB[mt] = h1b[(rA + 8) * 33 + kloc];
            }
#pragma unroll
            for (int ks = 0; ks < 4; ks++) {
                uint32_t b[4][2];
#pragma unroll
                for (int ni = 0; ni < 4; ni++) {
                    int orow = warpN * 32 + ni * 8 + g;
                    int ib = ks * 16 + 2 * t4;
                    b[ni][0] = *(const uint32_t*)&w2p[(cc * 64 + orow) * 72 + ib];
                    b[ni][1] = *(const uint32_t*)&w2p[(cc * 64 + orow) * 72 + ib + 8];
                }
#pragma unroll
                for (int mt = 0; mt < 2; mt++) {
                    uint32_t sa[4];
                    sa[0] = hmul2b(vfrag[mt][ks][0], hA[mt]);
                    sa[1] = hmul2b(vfrag[mt][ks][1], hB[mt]);
                    sa[2] = hmul2b(vfrag[mt][ks][2], hA[mt]);
                    sa[3] = hmul2b(vfrag[mt][ks][3], hB[mt]);
#pragma unroll
                    for (int ni = 0; ni < 4; ni++)
                        mma_bf16(c[mt][ni], sa, b[ni]);
                }
            }
        }
        __syncthreads();
    }

    // bias chunk (k=64, unit coefficient) — only khalf==1, in buf 0
    if (khalf == 1) {
        asm volatile("cp.async.wait_group 0;" ::: "memory");
        __syncthreads();
        const __nv_bfloat16* w2p = (const __nv_bfloat16*)(smem + MSG_SMEM_W2);
#pragma unroll
        for (int ks = 0; ks < 4; ks++) {
            uint32_t b[4][2];
#pragma unroll
            for (int ni = 0; ni < 4; ni++) {
                int orow = warpN * 32 + ni * 8 + g;
                int ib = ks * 16 + 2 * t4;
                b[ni][0] = *(const uint32_t*)&w2p[orow * 72 + ib];
                b[ni][1] = *(const uint32_t*)&w2p[orow * 72 + ib + 8];
            }
#pragma unroll
            for (int mt = 0; mt < 2; mt++)
#pragma unroll
                for (int ni = 0; ni < 4; ni++)
                    mma_bf16(c[mt][ni], vfrag[mt][ks], b[ni]);
        }
    }

    // scatter into agg
#pragma unroll
    for (int mt = 0; mt < 2; mt++)
#pragma unroll
        for (int half = 0; half < 2; half++) {
            int row = rowbase + mt * 16 + g + half * 8;
            int d = dssm[row];
            float* ap = &g_agg[(size_t)d * 64 + warpN * 32];
#pragma unroll
            for (int ni = 0; ni < 4; ni++) {
                atomicAdd(&ap[ni * 8 + 2 * t4],     c[mt][ni][half * 2 + 0]);
                atomicAdd(&ap[ni * 8 + 2 * t4 + 1], c[mt][ni][half * 2 + 1]);
            }
        }
}

// ---------------- tf32 NNConv epilogue + GRU (32 nodes/block, merged B+H pass) -----
// Pass 1 over hsm2 computes h@R^T (accB) AND h@Whh^T (accH): h loaded once, 4
// independent mma chains. Pass 2 computes m@Wih^T only. 2 CTAs/SM.
__global__ __launch_bounds__(256, 2) void node_update_tc(
    const float* __restrict__ cbias,
    const float* __restrict__ bih, const float* __restrict__ bhh) {
    __shared__ uint2 hsm2[32][36];
    __shared__ uint2 msm2[32][36];
    int n0 = blockIdx.x * 32;
    int tid = threadIdx.x;

    // stage h -> paired tf32 smem
#pragma unroll
    for (int i = 0; i < 4; i++) {
        int idx = tid + i * 256;                // 1024 = 32 rows x 32 pairs
        int row = idx >> 5, pr = idx & 31;
        int ks = pr >> 2, t4v = pr & 3;
        const float* hp = &g_h[(size_t)(n0 + row) * 64 + ks * 8 + t4v];
        uint2 u;
        u.x = f2tf32(hp[0]);
        u.y = f2tf32(hp[4]);
        hsm2[row][pr] = u;
    }
    __syncthreads();

    int w = tid >> 5, lane = tid & 31;
    int g = lane >> 2, t4 = lane & 3;
    int c0 = w * 8 + 2 * t4;
    int kk0 = c0 & 7;
    int idx32_0 = w * 8 + (kk0 & 3) * 2 + (kk0 >> 2);       // col c0
    int kk1 = (c0 + 1) & 7;
    int idx32_1 = w * 8 + (kk1 & 3) * 2 + (kk1 >> 2);       // col c0+1

    // ---- pass 1: h @ R^T  and  h @ Whh^T (single sweep over hsm2) ----
    float accB[2][4] = {};
    float accH[2][3][4] = {};
#pragma unroll
    for (int ks = 0; ks < 8; ks++) {
        uint2 rb2 = *(const uint2*)&g_rtu[(w * 8 + g) * 64 + ks * 8 + t4 * 2];
        uint32_t rb[2] = { rb2.x, rb2.y };
        uint32_t bh[3][2];
#pragma unroll
        for (int j = 0; j < 3; j++) {
            uint2 v = *(const uint2*)&g_whhTu[(j * 64 + w * 8 + g) * 64 + ks * 8 + t4 * 2];
            bh[j][0] = v.x; bh[j][1] = v.y;
        }
#pragma unroll
        for (int mt = 0; mt < 2; mt++) {
            int r0 = mt * 16 + g;
            uint2 u0 = hsm2[r0][ks * 4 + t4];
            uint2 u1 = hsm2[r0 + 8][ks * 4 + t4];
            uint32_t a[4] = { u0.x, u1.x, u0.y, u1.y };
            mma_tf32(accB[mt], a, rb);
#pragma unroll
            for (int j = 0; j < 3; j++)
                mma_tf32(accH[mt][j], a, bh[j]);
        }
    }
    // epilogue B: m = lrelu(agg*invdeg + h@R + cbias); zero agg; stage m paired tf32
    {
        float2 cb = *(const float2*)&cbias[c0];
#pragma unroll
        for (int mt = 0; mt < 2; mt++) {
#pragma unroll
            for (int half = 0; half < 2; half++) {
                int row = mt * 16 + g + half * 8;
                int node = n0 + row;
                float inv = g_deg[node];
                float2 ag = *(float2*)&g_agg[(size_t)node * 64 + c0];
                *(float2*)&g_agg[(size_t)node * 64 + c0] = make_float2(0.f, 0.f);
                float mx = lrelu(ag.x * inv + accB[mt][half * 2 + 0] + cb.x);
                float my = lrelu(ag.y * inv + accB[mt][half * 2 + 1] + cb.y);
                uint32_t* mrow = (uint32_t*)&msm2[row][0];
                mrow[idx32_0] = f2tf32(mx);
                mrow[idx32_1] = f2tf32(my);
            }
        }
    }
    __syncthreads();

    // ---- pass 2: gi = m @ Wih^T (3 gates x 8 cols per warp) ----
    float accI[2][3][4] = {};
#pragma unroll
    for (int ks = 0; ks < 8; ks++) {
        uint32_t bi[3][2];
#pragma unroll
        for (int j = 0; j < 3; j++) {
            uint2 u = *(const uint2*)&g_wihTu[(j * 64 + w * 8 + g) * 64 + ks * 8 + t4 * 2];
            bi[j][0] = u.x; bi[j][1] = u.y;
        }
#pragma unroll
        for (int mt = 0; mt < 2; mt++) {
            int r0 = mt * 16 + g;
            uint2 m0 = msm2[r0][ks * 4 + t4];
            uint2 m1 = msm2[r0 + 8][ks * 4 + t4];
            uint32_t am[4] = { m0.x, m1.x, m0.y, m1.y };
#pragma unroll
            for (int j = 0; j < 3; j++)
                mma_tf32(accI[mt][j], am, bi[j]);
        }
    }

    // epilogue C: GRU pointwise; hold reloaded exact from g_h
    float2 b_ir = *(const float2*)&bih[c0];
    float2 b_iz = *(const float2*)&bih[64 + c0];
    float2 b_in = *(const float2*)&bih[128 + c0];
    float2 b_hr = *(const float2*)&bhh[c0];
    float2 b_hz = *(const float2*)&bhh[64 + c0];
    float2 b_hn = *(const float2*)&bhh[128 + c0];
#pragma unroll
    for (int mt = 0; mt < 2; mt++) {
#pragma unroll
        for (int half = 0; half < 2; half++) {
            int row = mt * 16 + g + half * 8;
            int node = n0 + row;
            int o = half * 2;
            float2 hold = *(float2*)&g_h[(size_t)node * 64 + c0];
            float rx = sigm(accI[mt][0][o] + b_ir.x + accH[mt][0][o] + b_hr.x);
            float zx = sigm(accI[mt][1][o] + b_iz.x + accH[mt][1][o] + b_hz.x);
            float nx = tanhf(accI[mt][2][o] + b_in.x + rx * (accH[mt][2][o] + b_hn.x));
            float ry = sigm(accI[mt][0][o + 1] + b_ir.y + accH[mt][0][o + 1] + b_hr.y);
            float zy = sigm(accI[mt][1][o + 1] + b_iz.y + accH[mt][1][o + 1] + b_hz.y);
            float ny = tanhf(accI[mt][2][o + 1] + b_in.y + ry * (accH[mt][2][o + 1] + b_hn.y));
            float2 hn;
            hn.x = (1.f - zx) * nx + zx * hold.x;
            hn.y = (1.f - zy) * ny + zy * hold.y;
            *(float2*)&g_h[(size_t)node * 64 + c0] = hn;
        }
    }
}

// ---------------- stem head ----------------
__global__ __launch_bounds__(128) void stem_kernel(const int* __restrict__ idx,
                                                   const float* __restrict__ W1, const float* __restrict__ b1,
                                                   const float* __restrict__ W2, const float* __restrict__ b2,
                                                   float* __restrict__ outp) {
    __shared__ float row[64], hid[64];
    int s = blockIdx.x, t = threadIdx.x;
    int atom = idx[s];
    if (t < 64) row[t] = g_h[(size_t)atom * 64 + t];
    __syncthreads();
    if (t < 64) {
        float acc = b1[t];
#pragma unroll
        for (int i = 0; i < 64; i++) acc += row[i] * W1[i * 64 + t];
        hid[t] = lrelu(acc);
    }
    __syncthreads();
    for (int o = t; o < NUM_OUT; o += 128) {
        float acc = b2[o];
#pragma unroll
        for (int i = 0; i < 64; i++) acc += hid[i] * W2[i * NUM_OUT + o];
        outp[512 + (size_t)s * NUM_OUT + o] = acc;
    }
}

// ---------------- jbond head ----------------
__global__ __launch_bounds__(128) void jbond_kernel(const int* __restrict__ idx,
                                                    const float* __restrict__ W1, const float* __restrict__ b1,
                                                    const float* __restrict__ w2, const float* __restrict__ b2,
                                                    float* __restrict__ outp) {
    __shared__ float row[2][64];
    __shared__ float warpsum[4];
    int jb = blockIdx.x, t = threadIdx.x;
    int a = t >> 6, tt = t & 63;
    int atom = idx[jb * 2 + a];
    row[a][tt] = g_h[(size_t)atom * 64 + tt];
    __syncthreads();
    float acc = b1[tt];
#pragma unroll
    for (int i = 0; i < 64; i++) acc += row[a][i] * W1[i * 64 + tt];
    float p = lrelu(acc) * w2[tt];
#pragma unroll
    for (int off = 16; off; off >>= 1) p += __shfl_xor_sync(0xffffffffu, p, off);
    if ((t & 31) == 0) warpsum[t >> 5] = p;
    __syncthreads();
    if (t == 0) {
        float p0 = warpsum[0] + warpsum[1] + b2[0];
        float p1 = warpsum[2] + warpsum[3] + b2[0];
        outp[512 + (size_t)N_STEMS * NUM_OUT + jb] = 0.5f * (p0 + p1);
    }
}

// ---------------- Set2Set q (bias-only; identical for all graphs) ----------------
__global__ void s2s_q_kernel(const float* __restrict__ bih, const float* __restrict__ bhh) {
    int d = threadIdx.x;
    float bi = bih[d]       + bhh[d];
    float bg = bih[128 + d] + bhh[128 + d];
    float bo = bih[192 + d] + bhh[192 + d];
    float c = sigm(bi) * tanhf(bg);
    g_q[d] = sigm(bo) * tanhf(c);
}

// ---------------- per-graph attention pool + lin_out ----------------
__global__ __launch_bounds__(128) void pool_kernel(const int* __restrict__ batch,
                                                   const float* __restrict__ W, const float* __restrict__ bias,
                                                   float* __restrict__ outp) {
    __shared__ int s_lo, s_hi;
    __shared__ float s_max[4], s_ws[4], s_pool[4][64], s_r[64];
    int b = blockIdx.x, t = threadIdx.x;
    if (t == 0) {
        int lo = 0, hi = N_NODES;
        while (lo < hi) { int m = (lo + hi) >> 1; if (batch[m] < b) lo = m + 1; else hi = m; }
        s_lo = lo;
        int lo2 = lo, hi2 = N_NODES;
        while (lo2 < hi2) { int m = (lo2 + hi2) >> 1; if (batch[m] < b + 1) lo2 = m + 1; else hi2 = m; }
        s_hi = lo2;
    }
    __syncthreads();
    int lo = s_lo, hi = s_hi;
    int warp = t >> 5, lane = t & 31;
    float q0 = g_q[lane], q1 = g_q[32 + lane];
    float lmax = -3.4e38f;
    for (int n = lo + warp; n < hi; n += 4) {
        float v = g_h[(size_t)n * 64 + lane] * q0 + g_h[(size_t)n * 64 + 32 + lane] * q1;
#pragma unroll
        for (int off = 16; off; off >>= 1) v += __shfl_xor_sync(0xffffffffu, v, off);
        lmax = fmaxf(lmax, v);
    }
    if (lane == 0) s_max[warp] = lmax;
    __syncthreads();
    float emax = fmaxf(fmaxf(s_max[0], s_max[1]), fmaxf(s_max[2], s_max[3]));
    float p0 = 0.f, p1 = 0.f, ws = 0.f;
    for (int n = lo + warp; n < hi; n += 4) {
        float h0 = g_h[(size_t)n * 64 + lane], h1v = g_h[(size_t)n * 64 + 32 + lane];
        float v = h0 * q0 + h1v * q1;
#pragma unroll
        for (int off = 16; off; off >>= 1) v += __shfl_xor_sync(0xffffffffu, v, off);
        float c = expf(v - emax);
        p0 += c * h0; p1 += c * h1v; ws += c;
    }
    s_pool[warp][lane] = p0; s_pool[warp][32 + lane] = p1;
    if (lane == 0) s_ws[warp] = ws;
    __syncthreads();
    if (t < 64) {
        float ps = s_pool[0][t] + s_pool[1][t] + s_pool[2][t] + s_pool[3][t];
        float wtot = s_ws[0] + s_ws[1] + s_ws[2] + s_ws[3];
        s_r[t] = (wtot > 0.f) ? ps / wtot : 0.f;
    }
    __syncthreads();
    if (t < 2) {
        float acc = bias[t];
        for (int d = 0; d < 64; d++)
            acc += g_q[d] * W[d * 2 + t] + s_r[d] * W[(64 + d) * 2 + t];
        outp[b * 2 + t] = acc;
    }
}

// ---------------- launch ----------------
extern "C" void kernel_launch(void* const* d_in, const int* in_sizes, int n_in,
                              void* d_out, int out_size) {
    const float* x          = (const float*)d_in[0];
    const float* edge_attr  = (const float*)d_in[1];
    const int*   edge_index = (const int*)  d_in[2];
    const int*   batch      = (const int*)  d_in[3];
    const int*   stem_idx   = (const int*)  d_in[4];
    const int*   jbond_idx  = (const int*)  d_in[5];
    const float* lin0_w   = (const float*)d_in[6];
    const float* lin0_b   = (const float*)d_in[7];
    const float* net_w1   = (const float*)d_in[8];
    const float* net_b1   = (const float*)d_in[9];
    const float* net_w2   = (const float*)d_in[10];
    const float* net_b2   = (const float*)d_in[11];
    const float* conv_root= (const float*)d_in[12];
    const float* conv_bias= (const float*)d_in[13];
    const float* gru_w_ih = (const float*)d_in[14];
    const float* gru_w_hh = (const float*)d_in[15];
    const float* gru_b_ih = (const float*)d_in[16];
    const float* gru_b_hh = (const float*)d_in[17];
    const float* n2s_w1   = (const float*)d_in[18];
    const float* n2s_b1   = (const float*)d_in[19];
    const float* n2s_w2   = (const float*)d_in[20];
    const float* n2s_b2   = (const float*)d_in[21];
    const float* n2j_w1   = (const float*)d_in[22];
    const float* n2j_b1   = (const float*)d_in[23];
    const float* n2j_w2   = (const float*)d_in[24];
    const float* n2j_b2   = (const float*)d_in[25];
    const float* s2s_b_ih = (const float*)d_in[28];
    const float* s2s_b_hh = (const float*)d_in[29];
    const float* lin_out_w= (const float*)d_in[30];
    const float* lin_out_b= (const float*)d_in[31];
    float* out = (float*)d_out;

    const int* src = edge_index;             // edge_index[0]
    const int* dst = edge_index + N_EDGES;   // edge_index[1]

    cudaFuncSetAttribute(msg_gemm, cudaFuncAttributeMaxDynamicSharedMemorySize,
                         MSG_SMEM_TOTAL);

    zero_deg_kernel<<<N_NODES / 256, 256>>>();
    deg_kernel<<<(N_EDGES + 255) / 256, 256>>>(dst);
    invdeg_kernel<<<N_NODES / 256, 256>>>();
    zero_agg_kernel<<<N_NODES * DIM / 4 / 256, 256>>>();
    lin0_kernel<<<N_NODES * DIM / 256, 256>>>(x, lin0_w, lin0_b);
    h1_kernel<<<N_EDGES * DIM / 256, 256>>>(edge_attr, net_w1, net_b1);
    w2r_kernel<<<(65 * 4096 + 255) / 256, 256>>>(net_w2, net_b2);
    prep_weights_kernel<<<112, 256>>>(conv_root, gru_w_ih, gru_w_hh);

    for (int it = 0; it < 6; it++) {
        msg_gemm<<<256, 256, MSG_SMEM_TOTAL>>>(src, dst);
        node_update_tc<<<N_NODES / 32, 256>>>(conv_bias, gru_b_ih, gru_b_hh);
    }

    stem_kernel<<<N_STEMS, 128>>>(stem_idx, n2s_w1, n2s_b1, n2s_w2, n2s_b2, out);
    jbond_kernel<<<N_JBONDS, 128>>>(jbond_idx, n2j_w1, n2j_b1, n2j_w2, n2j_b2, out);
    s2s_q_kernel<<<1, 64>>>(s2s_b_ih, s2s_b_hh);
    pool_kernel<<<N_GRAPHS, 128>>>(batch, lin_out_w, lin_out_b, out);
}

// round 16
// speedup vs baseline: 1.0557x; 1.0557x over previous
#include <cuda_runtime.h>
#include <cuda_bf16.h>
#include <cstdint>
#include <math.h>

#define N_NODES   8192
#define N_EDGES   16384
#define N_GRAPHS  256
#define N_STEMS   2048
#define N_JBONDS  1024
#define DIM       64
#define NUM_FEAT  14
#define NUM_OUT   105

// ---------------- scratch (device globals; no allocations allowed) ----------------
__device__ __nv_bfloat16 g_w2r[65 * 64 * 64];   // W2 rearranged [chunk k][o][i] bf16; chunk 64 = B2
__device__ float g_h1f[N_EDGES * DIM];          // edge-net hidden (fp32)
__device__ uint32_t g_rtu[64 * 64];             // conv_root^T  [o][pair-permuted k] tf32 bits
__device__ uint32_t g_wihTu[192 * 64];          // gru_w_ih^T [o][pair-permuted k] tf32 bits
__device__ uint32_t g_whhTu[192 * 64];          // gru_w_hh^T [o][pair-permuted k] tf32 bits
__device__ float g_h[N_NODES * DIM];            // node state
__device__ float g_agg[N_NODES * DIM];          // scatter accumulator
__device__ float g_deg[N_NODES];                // becomes 1/max(deg,1)
__device__ float g_q[DIM];

__device__ __forceinline__ float lrelu(float v) { return v > 0.f ? v : 0.01f * v; }
__device__ __forceinline__ float sigm(float v)  { return 1.f / (1.f + expf(-v)); }

__device__ __forceinline__ void mma_bf16(float* c, const uint32_t* a, const uint32_t* b) {
    asm volatile(
        "mma.sync.aligned.m16n8k16.row.col.f32.bf16.bf16.f32 "
        "{%0,%1,%2,%3}, {%4,%5,%6,%7}, {%8,%9}, {%0,%1,%2,%3};"
        : "+f"(c[0]), "+f"(c[1]), "+f"(c[2]), "+f"(c[3])
        : "r"(a[0]), "r"(a[1]), "r"(a[2]), "r"(a[3]), "r"(b[0]), "r"(b[1]));
}

__device__ __forceinline__ uint32_t hmul2b(uint32_t a, uint32_t s) {
    uint32_t r;
    asm("mul.bf16x2 %0, %1, %2;" : "=r"(r) : "r"(a), "r"(s));
    return r;
}

__device__ __forceinline__ uint32_t f2tf32(float f) {
    uint32_t r;
    asm("cvt.rna.tf32.f32 %0, %1;" : "=r"(r) : "f"(f));
    return r;
}

__device__ __forceinline__ void mma_tf32(float* c, const uint32_t* a, const uint32_t* b) {
    asm volatile(
        "mma.sync.aligned.m16n8k8.row.col.f32.tf32.tf32.f32 "
        "{%0,%1,%2,%3}, {%4,%5,%6,%7}, {%8,%9}, {%0,%1,%2,%3};"
        : "+f"(c[0]), "+f"(c[1]), "+f"(c[2]), "+f"(c[3])
        : "r"(a[0]), "r"(a[1]), "r"(a[2]), "r"(a[3]), "r"(b[0]), "r"(b[1]));
}

// pair-permuted storage index: j = ks*8 + t4*2 + p  <->  k = ks*8 + t4 + 4*p
__device__ __forceinline__ int pp_k(int j) {
    return (j & ~7) + ((j & 7) >> 1) + (j & 1) * 4;
}

// ---------------- degree / init ----------------
__global__ void zero_deg_kernel() {
    g_deg[blockIdx.x * 256 + threadIdx.x] = 0.f;
}
__global__ void deg_kernel(const int* __restrict__ dst) {
    int e = blockIdx.x * 256 + threadIdx.x;
    if (e < N_EDGES) atomicAdd(&g_deg[dst[e]], 1.0f);
}
__global__ void invdeg_kernel() {
    int i = blockIdx.x * 256 + threadIdx.x;
    g_deg[i] = 1.0f / fmaxf(g_deg[i], 1.0f);
}
__global__ void zero_agg_kernel() {
    int i = blockIdx.x * 256 + threadIdx.x;
    ((float4*)g_agg)[i] = make_float4(0.f, 0.f, 0.f, 0.f);
}

// ---------------- lin0: h = lrelu(x @ W + b) ----------------
__global__ void lin0_kernel(const float* __restrict__ x,
                            const float* __restrict__ W,
                            const float* __restrict__ b) {
    int tid = blockIdx.x * 256 + threadIdx.x;
    int n = tid >> 6, o = tid & 63;
    float acc = b[o];
#pragma unroll
    for (int i = 0; i < NUM_FEAT; i++) acc += x[n * NUM_FEAT + i] * W[i * DIM + o];
    g_h[(size_t)n * DIM + o] = lrelu(acc);
}

// ---------------- edge net hidden: h1 = lrelu(ea @ W1 + b1), fp32 ----------------
__global__ void h1_kernel(const float* __restrict__ ea,
                          const float* __restrict__ W1,
                          const float* __restrict__ b1) {
    int tid = blockIdx.x * 256 + threadIdx.x;
    int e = tid >> 6, k = tid & 63;
    float acc = b1[k];
#pragma unroll
    for (int i = 0; i < 4; i++) acc += ea[e * 4 + i] * W1[i * DIM + k];
    g_h1f[(size_t)e * DIM + k] = lrelu(acc);
}

// ---------------- W2 rearrange: g_w2r[k][o][i] = W2[k][i*64+o]; chunk 64 = B2 ------
__global__ void w2r_kernel(const float* __restrict__ W2, const float* __restrict__ b2) {
    int idx = blockIdx.x * 256 + threadIdx.x;
    if (idx >= 65 * 4096) return;
    int c = idx >> 12, r = idx & 4095;
    int o = r >> 6, i = r & 63;
    float v = (c < 64) ? W2[(c << 12) + (i << 6) + o] : b2[(i << 6) + o];
    g_w2r[idx] = __float2bfloat16(v);
}

// ---------------- GRU/root weights -> transposed, pair-permuted tf32 bits ----------
__global__ void prep_weights_kernel(const float* __restrict__ R,
                                    const float* __restrict__ Wih,
                                    const float* __restrict__ Whh) {
    int i = blockIdx.x * 256 + threadIdx.x;     // 0 .. 28671
    if (i < 4096) {
        int o = i >> 6, j = i & 63;
        g_rtu[o * 64 + j] = f2tf32(R[pp_k(j) * 64 + o]);
    } else if (i < 4096 + 12288) {
        int q = i - 4096;
        int o = q >> 6, j = q & 63;
        g_wihTu[o * 64 + j] = f2tf32(Wih[pp_k(j) * 192 + o]);
    } else {
        int q = i - 4096 - 12288;
        int o = q >> 6, j = q & 63;
        g_whhTu[o * 64 + j] = f2tf32(Whh[pp_k(j) * 192 + o]);
    }
}

// ================= fused factorized message GEMM (k-split, ldmatrix B) ============
#define MSG_SMEM_W2   0
#define MSG_SMEM_V    73728
#define MSG_SMEM_H1   92160
#define MSG_SMEM_DS   109056
#define MSG_SMEM_SS   109568
#define MSG_SMEM_TOTAL 110080
#define W2BUF_BYTES   36864

__device__ __forceinline__ void prefetch_w2(int base_chunk, int nch, int buf,
                                            int tid, uint32_t smem_base) {
    int tasks = nch * 512;                      // nch * 64 rows * 8 segs
    for (int idx = tid; idx < tasks; idx += 256) {
        int cc = idx >> 9;
        int o  = (idx >> 3) & 63;
        int s  = idx & 7;
        const __nv_bfloat16* gp = &g_w2r[((size_t)(base_chunk + cc) * 64 + o) * 64 + s * 8];
        uint32_t sp = smem_base + MSG_SMEM_W2 + buf * W2BUF_BYTES
                      + ((cc * 64 + o) * 72 + s * 8) * 2;
        asm volatile("cp.async.cg.shared.global [%0], [%1], 16;" :: "r"(sp), "l"(gp));
    }
    asm volatile("cp.async.commit_group;" ::: "memory");
}

__global__ __launch_bounds__(256, 2) void msg_gemm(const int* __restrict__ src,
                                                   const int* __restrict__ dst) {
    extern __shared__ char smem[];
    __nv_bfloat16* vsm = (__nv_bfloat16*)(smem + MSG_SMEM_V);
    uint32_t* h1b = (uint32_t*)(smem + MSG_SMEM_H1);
    int* dssm = (int*)(smem + MSG_SMEM_DS);
    int* ssm  = (int*)(smem + MSG_SMEM_SS);
    uint32_t smem_base = (uint32_t)__cvta_generic_to_shared(smem);

    int tid = threadIdx.x;
    int ebid = blockIdx.x & 127;
    int khalf = blockIdx.x >> 7;
    int e0 = ebid * 128;
    int kbase = khalf * 32;

    if (tid < 128) {
        ssm[tid] = src[e0 + tid];
        dssm[tid] = dst[e0 + tid];
    }
    prefetch_w2(kbase, 4, 0, tid, smem_base);
    __syncthreads();                            // ssm visible

#pragma unroll
    for (int p = 0; p < 8; p++) {
        int idx = tid + p * 256;                // 2048 tasks: 128 rows x 16 segs
        int row = idx >> 4, seg = idx & 15;
        int s = ssm[row];
        float4 v = *(const float4*)&g_h[(size_t)s * 64 + seg * 4];
        __nv_bfloat162 p0 = __floats2bfloat162_rn(v.x, v.y);
        __nv_bfloat162 p1 = __floats2bfloat162_rn(v.z, v.w);
        uint2 u; u.x = *(uint32_t*)&p0; u.y = *(uint32_t*)&p1;
        *(uint2*)&vsm[row * 72 + seg * 4] = u;
    }
#pragma unroll
    for (int p = 0; p < 4; p++) {
        int idx = tid + p * 256;                // 1024 tasks: 128 rows x 8 quads
        int row = idx >> 3, q = idx & 7;
        float4 hv = *(const float4*)&g_h1f[(size_t)(e0 + row) * 64 + kbase + q * 4];
        __nv_bfloat16 b0 = __float2bfloat16(hv.x);
        __nv_bfloat16 b1 = __float2bfloat16(hv.y);
        __nv_bfloat16 b2 = __float2bfloat16(hv.z);
        __nv_bfloat16 b3 = __float2bfloat16(hv.w);
        h1b[row * 33 + q * 4 + 0] = ((uint32_t)*(uint16_t*)&b0) * 0x00010001u;
        h1b[row * 33 + q * 4 + 1] = ((uint32_t)*(uint16_t*)&b1) * 0x00010001u;
        h1b[row * 33 + q * 4 + 2] = ((uint32_t)*(uint16_t*)&b2) * 0x00010001u;
        h1b[row * 33 + q * 4 + 3] = ((uint32_t)*(uint16_t*)&b3) * 0x00010001u;
    }
    __syncthreads();

    int w = tid >> 5, lane = tid & 31;
    int warpM = w >> 1, warpN = w & 1;          // 4 m-warps x 2 n-warps
    int rowbase = warpM * 32;
    int g = lane >> 2, t4 = lane & 3;

    // ldmatrix lane offsets: tile t = lane>>3 maps to (ni = t>>1, kh = t&1), row = lane&7
    int tloc = lane >> 3, rrow = lane & 7;
    uint32_t laneoffA = (uint32_t)(((warpN * 32 + (tloc >> 1) * 8 + rrow) * 72
                                    + (tloc & 1) * 8) * 2);       // ni 0,1
    uint32_t laneoffB = laneoffA + 16u * 72u * 2u;                // ni 2,3

    uint32_t vfrag[2][4][4];
#pragma unroll
    for (int mt = 0; mt < 2; mt++)
#pragma unroll
        for (int ks = 0; ks < 4; ks++) {
            int r0 = rowbase + mt * 16 + g;
            int cl = ks * 16 + 2 * t4;
            vfrag[mt][ks][0] = *(const uint32_t*)&vsm[r0 * 72 + cl];
            vfrag[mt][ks][1] = *(const uint32_t*)&vsm[(r0 + 8) * 72 + cl];
            vfrag[mt][ks][2] = *(const uint32_t*)&vsm[r0 * 72 + cl + 8];
            vfrag[mt][ks][3] = *(const uint32_t*)&vsm[(r0 + 8) * 72 + cl + 8];
        }

    float c[2][4][4];
#pragma unroll
    for (int mt = 0; mt < 2; mt++)
#pragma unroll
        for (int ni = 0; ni < 4; ni++)
#pragma unroll
            for (int r = 0; r < 4; r++) c[mt][ni][r] = 0.f;

#pragma unroll 1
    for (int grp = 0; grp < 8; grp++) {
        asm volatile("cp.async.wait_group 0;" ::: "memory");
        __syncthreads();
        int buf = grp & 1;
        if (grp < 7)           prefetch_w2(kbase + (grp + 1) * 4, 4, (grp + 1) & 1, tid, smem_base);
        else if (khalf == 1)   prefetch_w2(64, 1, 0, tid, smem_base);
        uint32_t w2s = smem_base + MSG_SMEM_W2 + buf * W2BUF_BYTES;
#pragma unroll 1
        for (int cc = 0; cc < 4; cc++) {
            int kloc = grp * 4 + cc;
            uint32_t ccoff = (uint32_t)cc * 9216u;
            uint32_t hA[2], hB[2];
#pragma unroll
            for (int mt = 0; mt < 2; mt++) {
                int rA = rowbase + mt * 16 + g;
                hA[mt] = h1b[rA * 33 + kloc];
                hB[mt] = h1b[(rA + 8) * 33 + kloc];
            }
#pragma unroll
            for (int ks = 0; ks < 4; ks++) {
                uint32_t b[4][2];
                {
                    uint32_t addrA = w2s + ccoff + (uint32_t)(ks * 32) + laneoffA;
                    uint32_t addrB = w2s + ccoff + (uint32_t)(ks * 32) + laneoffB;
                    asm volatile(
                        "ldmatrix.sync.aligned.m8n8.x4.shared.b16 {%0,%1,%2,%3}, [%4];"
                        : "=r"(b[0][0]), "=r"(b[0][1]), "=r"(b[1][0]), "=r"(b[1][1])
                        : "r"(addrA));
                    asm volatile(
                        "ldmatrix.sync.aligned.m8n8.x4.shared.b16 {%0,%1,%2,%3}, [%4];"
                        : "=r"(b[2][0]), "=r"(b[2][1]), "=r"(b[3][0]), "=r"(b[3][1])
                        : "r"(addrB));
                }
#pragma unroll
                for (int mt = 0; mt < 2; mt++) {
                    uint32_t sa[4];
                    sa[0] = hmul2b(vfrag[mt][ks][0], hA[mt]);
                    sa[1] = hmul2b(vfrag[mt][ks][1], hB[mt]);
                    sa[2] = hmul2b(vfrag[mt][ks][2], hA[mt]);
                    sa[3] = hmul2b(vfrag[mt][ks][3], hB[mt]);
#pragma unroll
                    for (int ni = 0; ni < 4; ni++)
                        mma_bf16(c[mt][ni], sa, b[ni]);
                }
            }
        }
        __syncthreads();
    }

    // bias chunk (k=64, unit coefficient) — only khalf==1, in buf 0
    if (khalf == 1) {
        asm volatile("cp.async.wait_group 0;" ::: "memory");
        __syncthreads();
        const __nv_bfloat16* w2p = (const __nv_bfloat16*)(smem + MSG_SMEM_W2);
#pragma unroll
        for (int ks = 0; ks < 4; ks++) {
            uint32_t b[4][2];
#pragma unroll
            for (int ni = 0; ni < 4; ni++) {
                int orow = warpN * 32 + ni * 8 + g;
                int ib = ks * 16 + 2 * t4;
                b[ni][0] = *(const uint32_t*)&w2p[orow * 72 + ib];
                b[ni][1] = *(const uint32_t*)&w2p[orow * 72 + ib + 8];
            }
#pragma unroll
            for (int mt = 0; mt < 2; mt++)
#pragma unroll
                for (int ni = 0; ni < 4; ni++)
                    mma_bf16(c[mt][ni], vfrag[mt][ks], b[ni]);
        }
    }

    // scatter into agg
#pragma unroll
    for (int mt = 0; mt < 2; mt++)
#pragma unroll
        for (int half = 0; half < 2; half++) {
            int row = rowbase + mt * 16 + g + half * 8;
            int d = dssm[row];
            float* ap = &g_agg[(size_t)d * 64 + warpN * 32];
#pragma unroll
            for (int ni = 0; ni < 4; ni++) {
                atomicAdd(&ap[ni * 8 + 2 * t4],     c[mt][ni][half * 2 + 0]);
                atomicAdd(&ap[ni * 8 + 2 * t4 + 1], c[mt][ni][half * 2 + 1]);
            }
        }
}

// ---------------- tf32 NNConv epilogue + GRU (32 nodes/block, grid 256, 2 CTA/SM) --
// R14 structure (separate B and C phases, paired loads).
__global__ __launch_bounds__(256, 2) void node_update_tc(
    const float* __restrict__ cbias,
    const float* __restrict__ bih, const float* __restrict__ bhh) {
    __shared__ uint2 hsm2[32][36];
    __shared__ uint2 msm2[32][36];
    int n0 = blockIdx.x * 32;
    int tid = threadIdx.x;

    // stage h -> paired tf32 smem
#pragma unroll
    for (int i = 0; i < 4; i++) {
        int idx = tid + i * 256;                // 1024 = 32 rows x 32 pairs
        int row = idx >> 5, pr = idx & 31;
        int ks = pr >> 2, t4v = pr & 3;
        const float* hp = &g_h[(size_t)(n0 + row) * 64 + ks * 8 + t4v];
        uint2 u;
        u.x = f2tf32(hp[0]);
        u.y = f2tf32(hp[4]);
        hsm2[row][pr] = u;
    }
    __syncthreads();

    int w = tid >> 5, lane = tid & 31;
    int g = lane >> 2, t4 = lane & 3;
    int c0 = w * 8 + 2 * t4;
    int kk0 = c0 & 7;
    int idx32_0 = w * 8 + (kk0 & 3) * 2 + (kk0 >> 2);       // col c0
    int kk1 = (c0 + 1) & 7;
    int idx32_1 = w * 8 + (kk1 & 3) * 2 + (kk1 >> 2);       // col c0+1

    // ---- phase B: h @ R^T ----
    float accB[2][4] = {};
#pragma unroll
    for (int ks = 0; ks < 8; ks++) {
        uint2 rb2 = *(const uint2*)&g_rtu[(w * 8 + g) * 64 + ks * 8 + t4 * 2];
        uint32_t rb[2] = { rb2.x, rb2.y };
#pragma unroll
        for (int mt = 0; mt < 2; mt++) {
            int r0 = mt * 16 + g;
            uint2 u0 = hsm2[r0][ks * 4 + t4];
            uint2 u1 = hsm2[r0 + 8][ks * 4 + t4];
            uint32_t a[4] = { u0.x, u1.x, u0.y, u1.y };
            mma_tf32(accB[mt], a, rb);
        }
    }
    // epilogue B: m = lrelu(agg*invdeg + h@R + cbias); zero agg; stage m paired tf32
    {
        float2 cb = *(const float2*)&cbias[c0];
#pragma unroll
        for (int mt = 0; mt < 2; mt++) {
#pragma unroll
            for (int half = 0; half < 2; half++) {
                int row = mt * 16 + g + half * 8;
                int node = n0 + row;
                float inv = g_deg[node];
                float2 ag = *(float2*)&g_agg[(size_t)node * 64 + c0];
                *(float2*)&g_agg[(size_t)node * 64 + c0] = make_float2(0.f, 0.f);
                float mx = lrelu(ag.x * inv + accB[mt][half * 2 + 0] + cb.x);
                float my = lrelu(ag.y * inv + accB[mt][half * 2 + 1] + cb.y);
                uint32_t* mrow = (uint32_t*)&msm2[row][0];
                mrow[idx32_0] = f2tf32(mx);
                mrow[idx32_1] = f2tf32(my);
            }
        }
    }
    __syncthreads();

    // ---- phase C: gi = m @ Wih^T, gh = h @ Whh^T (3 gates x 8 cols per warp) ----
    float accI[2][3][4] = {};
    float accH[2][3][4] = {};
#pragma unroll
    for (int ks = 0; ks < 8; ks++) {
        uint32_t bi[3][2], bh[3][2];
#pragma unroll
        for (int j = 0; j < 3; j++) {
            uint2 u = *(const uint2*)&g_wihTu[(j * 64 + w * 8 + g) * 64 + ks * 8 + t4 * 2];
            bi[j][0] = u.x; bi[j][1] = u.y;
            uint2 v = *(const uint2*)&g_whhTu[(j * 64 + w * 8 + g) * 64 + ks * 8 + t4 * 2];
            bh[j][0] = v.x; bh[j][1] = v.y;
        }
#pragma unroll
        for (int mt = 0; mt < 2; mt++) {
            int r0 = mt * 16 + g;
            uint2 m0 = msm2[r0][ks * 4 + t4];
            uint2 m1 = msm2[r0 + 8][ks * 4 + t4];
            uint2 h0 = hsm2[r0][ks * 4 + t4];
            uint2 h1 = hsm2[r0 + 8][ks * 4 + t4];
            uint32_t am[4] = { m0.x, m1.x, m0.y, m1.y };
            uint32_t ah[4] = { h0.x, h1.x, h0.y, h1.y };
#pragma unroll
            for (int j = 0; j < 3; j++) {
                mma_tf32(accI[mt][j], am, bi[j]);
                mma_tf32(accH[mt][j], ah, bh[j]);
            }
        }
    }

    // epilogue C: GRU pointwise; hold reloaded exact from g_h
    float2 b_ir = *(const float2*)&bih[c0];
    float2 b_iz = *(const float2*)&bih[64 + c0];
    float2 b_in = *(const float2*)&bih[128 + c0];
    float2 b_hr = *(const float2*)&bhh[c0];
    float2 b_hz = *(const float2*)&bhh[64 + c0];
    float2 b_hn = *(const float2*)&bhh[128 + c0];
#pragma unroll
    for (int mt = 0; mt < 2; mt++) {
#pragma unroll
        for (int half = 0; half < 2; half++) {
            int row = mt * 16 + g + half * 8;
            int node = n0 + row;
            int o = half * 2;
            float2 hold = *(float2*)&g_h[(size_t)node * 64 + c0];
            float rx = sigm(accI[mt][0][o] + b_ir.x + accH[mt][0][o] + b_hr.x);
            float zx = sigm(accI[mt][1][o] + b_iz.x + accH[mt][1][o] + b_hz.x);
            float nx = tanhf(accI[mt][2][o] + b_in.x + rx * (accH[mt][2][o] + b_hn.x));
            float ry = sigm(accI[mt][0][o + 1] + b_ir.y + accH[mt][0][o + 1] + b_hr.y);
            float zy = sigm(accI[mt][1][o + 1] + b_iz.y + accH[mt][1][o + 1] + b_hz.y);
            float ny = tanhf(accI[mt][2][o + 1] + b_in.y + ry * (accH[mt][2][o + 1] + b_hn.y));
            float2 hn;
            hn.x = (1.f - zx) * nx + zx * hold.x;
            hn.y = (1.f - zy) * ny + zy * hold.y;
            *(float2*)&g_h[(size_t)node * 64 + c0] = hn;
        }
    }
}

// ---------------- stem head ----------------
__global__ __launch_bounds__(128) void stem_kernel(const int* __restrict__ idx,
                                                   const float* __restrict__ W1, const float* __restrict__ b1,
                                                   const float* __restrict__ W2, const float* __restrict__ b2,
                                                   float* __restrict__ outp) {
    __shared__ float row[64], hid[64];
    int s = blockIdx.x, t = threadIdx.x;
    int atom = idx[s];
    if (t < 64) row[t] = g_h[(size_t)atom * 64 + t];
    __syncthreads();
    if (t < 64) {
        float acc = b1[t];
#pragma unroll
        for (int i = 0; i < 64; i++) acc += row[i] * W1[i * 64 + t];
        hid[t] = lrelu(acc);
    }
    __syncthreads();
    for (int o = t; o < NUM_OUT; o += 128) {
        float acc = b2[o];
#pragma unroll
        for (int i = 0; i < 64; i++) acc += hid[i] * W2[i * NUM_OUT + o];
        outp[512 + (size_t)s * NUM_OUT + o] = acc;
    }
}

// ---------------- jbond head ----------------
__global__ __launch_bounds__(128) void jbond_kernel(const int* __restrict__ idx,
                                                    const float* __restrict__ W1, const float* __restrict__ b1,
                                                    const float* __restrict__ w2, const float* __restrict__ b2,
                                                    float* __restrict__ outp) {
    __shared__ float row[2][64];
    __shared__ float warpsum[4];
    int jb = blockIdx.x, t = threadIdx.x;
    int a = t >> 6, tt = t & 63;
    int atom = idx[jb * 2 + a];
    row[a][tt] = g_h[(size_t)atom * 64 + tt];
    __syncthreads();
    float acc = b1[tt];
#pragma unroll
    for (int i = 0; i < 64; i++) acc += row[a][i] * W1[i * 64 + tt];
    float p = lrelu(acc) * w2[tt];
#pragma unroll
    for (int off = 16; off; off >>= 1) p += __shfl_xor_sync(0xffffffffu, p, off);
    if ((t & 31) == 0) warpsum[t >> 5] = p;
    __syncthreads();
    if (t == 0) {
        float p0 = warpsum[0] + warpsum[1] + b2[0];
        float p1 = warpsum[2] + warpsum[3] + b2[0];
        outp[512 + (size_t)N_STEMS * NUM_OUT + jb] = 0.5f * (p0 + p1);
    }
}

// ---------------- Set2Set q (bias-only; identical for all graphs) ----------------
__global__ void s2s_q_kernel(const float* __restrict__ bih, const float* __restrict__ bhh) {
    int d = threadIdx.x;
    float bi = bih[d]       + bhh[d];
    float bg = bih[128 + d] + bhh[128 + d];
    float bo = bih[192 + d] + bhh[192 + d];
    float c = sigm(bi) * tanhf(bg);
    g_q[d] = sigm(bo) * tanhf(c);
}

// ---------------- per-graph attention pool + lin_out ----------------
__global__ __launch_bounds__(128) void pool_kernel(const int* __restrict__ batch,
                                                   const float* __restrict__ W, const float* __restrict__ bias,
                                                   float* __restrict__ outp) {
    __shared__ int s_lo, s_hi;
    __shared__ float s_max[4], s_ws[4], s_pool[4][64], s_r[64];
    int b = blockIdx.x, t = threadIdx.x;
    if (t == 0) {
        int lo = 0, hi = N_NODES;
        while (lo < hi) { int m = (lo + hi) >> 1; if (batch[m] < b) lo = m + 1; else hi = m; }
        s_lo = lo;
        int lo2 = lo, hi2 = N_NODES;
        while (lo2 < hi2) { int m = (lo2 + hi2) >> 1; if (batch[m] < b + 1) lo2 = m + 1; else hi2 = m; }
        s_hi = lo2;
    }
    __syncthreads();
    int lo = s_lo, hi = s_hi;
    int warp = t >> 5, lane = t & 31;
    float q0 = g_q[lane], q1 = g_q[32 + lane];
    float lmax = -3.4e38f;
    for (int n = lo + warp; n < hi; n += 4) {
        float v = g_h[(size_t)n * 64 + lane] * q0 + g_h[(size_t)n * 64 + 32 + lane] * q1;
#pragma unroll
        for (int off = 16; off; off >>= 1) v += __shfl_xor_sync(0xffffffffu, v, off);
        lmax = fmaxf(lmax, v);
    }
    if (lane == 0) s_max[warp] = lmax;
    __syncthreads();
    float emax = fmaxf(fmaxf(s_max[0], s_max[1]), fmaxf(s_max[2], s_max[3]));
    float p0 = 0.f, p1 = 0.f, ws = 0.f;
    for (int n = lo + warp; n < hi; n += 4) {
        float h0 = g_h[(size_t)n * 64 + lane], h1v = g_h[(size_t)n * 64 + 32 + lane];
        float v = h0 * q0 + h1v * q1;
#pragma unroll
        for (int off = 16; off; off >>= 1) v += __shfl_xor_sync(0xffffffffu, v, off);
        float c = expf(v - emax);
        p0 += c * h0; p1 += c * h1v; ws += c;
    }
    s_pool[warp][lane] = p0; s_pool[warp][32 + lane] = p1;
    if (lane == 0) s_ws[warp] = ws;
    __syncthreads();
    if (t < 64) {
        float ps = s_pool[0][t] + s_pool[1][t] + s_pool[2][t] + s_pool[3][t];
        float wtot = s_ws[0] + s_ws[1] + s_ws[2] + s_ws[3];
        s_r[t] = (wtot > 0.f) ? ps / wtot : 0.f;
    }
    __syncthreads();
    if (t < 2) {
        float acc = bias[t];
        for (int d = 0; d < 64; d++)
            acc += g_q[d] * W[d * 2 + t] + s_r[d] * W[(64 + d) * 2 + t];
        outp[b * 2 + t] = acc;
    }
}

// ---------------- launch ----------------
extern "C" void kernel_launch(void* const* d_in, const int* in_sizes, int n_in,
                              void* d_out, int out_size) {
    const float* x          = (const float*)d_in[0];
    const float* edge_attr  = (const float*)d_in[1];
    const int*   edge_index = (const int*)  d_in[2];
    const int*   batch      = (const int*)  d_in[3];
    const int*   stem_idx   = (const int*)  d_in[4];
    const int*   jbond_idx  = (const int*)  d_in[5];
    const float* lin0_w   = (const float*)d_in[6];
    const float* lin0_b   = (const float*)d_in[7];
    const float* net_w1   = (const float*)d_in[8];
    const float* net_b1   = (const float*)d_in[9];
    const float* net_w2   = (const float*)d_in[10];
    const float* net_b2   = (const float*)d_in[11];
    const float* conv_root= (const float*)d_in[12];
    const float* conv_bias= (const float*)d_in[13];
    const float* gru_w_ih = (const float*)d_in[14];
    const float* gru_w_hh = (const float*)d_in[15];
    const float* gru_b_ih = (const float*)d_in[16];
    const float* gru_b_hh = (const float*)d_in[17];
    const float* n2s_w1   = (const float*)d_in[18];
    const float* n2s_b1   = (const float*)d_in[19];
    const float* n2s_w2   = (const float*)d_in[20];
    const float* n2s_b2   = (const float*)d_in[21];
    const float* n2j_w1   = (const float*)d_in[22];
    const float* n2j_b1   = (const float*)d_in[23];
    const float* n2j_w2   = (const float*)d_in[24];
    const float* n2j_b2   = (const float*)d_in[25];
    const float* s2s_b_ih = (const float*)d_in[28];
    const float* s2s_b_hh = (const float*)d_in[29];
    const float* lin_out_w= (const float*)d_in[30];
    const float* lin_out_b= (const float*)d_in[31];
    float* out = (float*)d_out;

    const int* src = edge_index;             // edge_index[0]
    const int* dst = edge_index + N_EDGES;   // edge_index[1]

    cudaFuncSetAttribute(msg_gemm, cudaFuncAttributeMaxDynamicSharedMemorySize,
                         MSG_SMEM_TOTAL);

    zero_deg_kernel<<<N_NODES / 256, 256>>>();
    deg_kernel<<<(N_EDGES + 255) / 256, 256>>>(dst);
    invdeg_kernel<<<N_NODES / 256, 256>>>();
    zero_agg_kernel<<<N_NODES * DIM / 4 / 256, 256>>>();
    lin0_kernel<<<N_NODES * DIM / 256, 256>>>(x, lin0_w, lin0_b);
    h1_kernel<<<N_EDGES * DIM / 256, 256>>>(edge_attr, net_w1, net_b1);
    w2r_kernel<<<(65 * 4096 + 255) / 256, 256>>>(net_w2, net_b2);
    prep_weights_kernel<<<112, 256>>>(conv_root, gru_w_ih, gru_w_hh);

    for (int it = 0; it < 6; it++) {
        msg_gemm<<<256, 256, MSG_SMEM_TOTAL>>>(src, dst);
        node_update_tc<<<N_NODES / 32, 256>>>(conv_bias, gru_b_ih, gru_b_hh);
    }

    stem_kernel<<<N_STEMS, 128>>>(stem_idx, n2s_w1, n2s_b1, n2s_w2, n2s_b2, out);
    jbond_kernel<<<N_JBONDS, 128>>>(jbond_idx, n2j_w1, n2j_b1, n2j_w2, n2j_b2, out);
    s2s_q_kernel<<<1, 64>>>(s2s_b_ih, s2s_b_hh);
    pool_kernel<<<N_GRAPHS, 128>>>(batch, lin_out_w, lin_out_b, out);
}